// round 4
// baseline (speedup 1.0000x reference)
#include <cuda_runtime.h>

#define NSEQ   10400     // B*S = 32*325
#define LSTEPS 192       // L
#define HID    128       // D_MODEL
#define NH     8
#define SLEN   325
#define NB     32
#define SCALE  0.08838834764831845f  // 1/sqrt(128)

// ---------------- scratch (static device arrays; no allocation) ----------------
__device__ float g_xT[LSTEPS * NSEQ];          //  8 MB  x transposed [l][n]
__device__ float g_Wt2[16 * HID * 512];        //  4 MB  gate-interleaved W^T [hq][k][j*4+g]
__device__ float g_bias2[16 * 512];            //         bih+bhh, interleaved
__device__ float g_wih2[16 * 512];             //         Wih col, interleaved
__device__ float g_q[NH * NSEQ * HID];         // 43 MB  q final hidden [h][n][d]
__device__ float g_kT[NH * HID * NSEQ];        // 43 MB  k final hidden transposed [h][d][n]
__device__ float g_v[NH * NSEQ * LSTEPS];      // 64 MB  v full outputs [h][n][l]

__device__ __forceinline__ float sigf(float x) { return 1.f / (1.f + __expf(-x)); }

// ---- packed f32x2 helpers (FFMA2 path: 2x fp32 FMA throughput on sm_103a) ----
__device__ __forceinline__ unsigned long long pk2(float lo, float hi) {
    unsigned long long r;
    asm("mov.b64 %0, {%1, %2};" : "=l"(r) : "f"(lo), "f"(hi));
    return r;
}
__device__ __forceinline__ void unpk2(unsigned long long v, float& lo, float& hi) {
    asm("mov.b64 {%0, %1}, %2;" : "=f"(lo), "=f"(hi) : "l"(v));
}
__device__ __forceinline__ unsigned long long ffma2(unsigned long long a,
                                                    unsigned long long b,
                                                    unsigned long long c) {
    unsigned long long d;
    asm("fma.rn.f32x2 %0, %1, %2, %3;" : "=l"(d) : "l"(a), "l"(b), "l"(c));
    return d;
}

// ---------------- prep: transpose x to [l][n] ----------------
__global__ void k_prep_x(const float* __restrict__ x) {
    int i = blockIdx.x * 256 + threadIdx.x;
    if (i < LSTEPS * NSEQ) {
        int l = i / NSEQ, n = i % NSEQ;
        g_xT[i] = x[(size_t)n * LSTEPS + l];
    }
}

// ---------------- prep: gate-interleaved transposed weights ----------------
// Wt2[hq][k][j*4+g] = Whh[h][g*128+j][k]   (hq<8: q-lstm head hq, else k-lstm head hq-8)
__global__ void k_prep_w(const float* __restrict__ qWih, const float* __restrict__ qWhh,
                         const float* __restrict__ qbih, const float* __restrict__ qbhh,
                         const float* __restrict__ kWih, const float* __restrict__ kWhh,
                         const float* __restrict__ kbih, const float* __restrict__ kbhh) {
    int idx = blockIdx.x * 256 + threadIdx.x;
    if (idx >= 16 * HID * 512) return;
    int hq   = idx / (HID * 512);
    int rem  = idx % (HID * 512);
    int k    = rem / 512;
    int cidx = rem % 512;
    int j = cidx >> 2, g = cidx & 3;
    int row = g * HID + j;
    int h = hq & 7;
    const float* Whh = (hq < 8) ? (qWhh + (size_t)h * 512 * HID) : (kWhh + (size_t)h * 512 * HID);
    g_Wt2[idx] = Whh[row * HID + k];
    if (k == 0) {
        const float* Wih = (hq < 8) ? qWih + h * 512 : kWih + h * 512;
        const float* bi  = (hq < 8) ? qbih + h * 512 : kbih + h * 512;
        const float* bh  = (hq < 8) ? qbhh + h * 512 : kbhh + h * 512;
        g_wih2[hq * 512 + cidx]  = Wih[row];
        g_bias2[hq * 512 + cidx] = bi[row] + bh[row];
    }
}

// ---------------- v LSTM: hidden size 1, one thread per (head, seq) ----------------
__global__ void k_v_lstm(const float* __restrict__ wih, const float* __restrict__ whh,
                         const float* __restrict__ bih, const float* __restrict__ bhh) {
    int idx = blockIdx.x * 256 + threadIdx.x;
    if (idx >= NH * NSEQ) return;
    int h = idx / NSEQ, n = idx % NSEQ;
    float wi[4], wh[4], bb[4];
#pragma unroll
    for (int g = 0; g < 4; g++) {
        wi[g] = wih[h * 4 + g];
        wh[g] = whh[h * 4 + g];
        bb[g] = bih[h * 4 + g] + bhh[h * 4 + g];
    }
    float hv = 0.f, cv = 0.f;
    float* vp = g_v + (size_t)idx * LSTEPS;
    for (int t = 0; t < LSTEPS; t++) {
        float xv = g_xT[t * NSEQ + n];
        float zi = wi[0] * xv + wh[0] * hv + bb[0];
        float zf = wi[1] * xv + wh[1] * hv + bb[1];
        float zg = wi[2] * xv + wh[2] * hv + bb[2];
        float zo = wi[3] * xv + wh[3] * hv + bb[3];
        cv = sigf(zf) * cv + sigf(zi) * tanhf(zg);
        hv = sigf(zo) * tanhf(cv);
        vp[t] = hv;
    }
}

// ---------------- q/k LSTM: persistent tile of 64 seqs, 512 threads ----------------
// thread (cx = tid&63, sy = tid>>6): 8 seqs (sy*8..) x 2 hidden units (cx*2..), all 4 gates.
// c stays in registers; h lives in smem (GEMM operand next step). z never materialized.
// Inner product uses packed fma.rn.f32x2 (FFMA2) for 2x fp32 throughput.
__global__ __launch_bounds__(512, 1) void k_qk_lstm() {
    int hq = blockIdx.y;
    int n0 = blockIdx.x * 64;
    int tid = threadIdx.x;
    int cx = tid & 63, sy = tid >> 6;

    __shared__ float hsm[64][HID];
    __shared__ float xs[64];

    for (int i = tid; i < 64 * HID; i += 512) ((float*)hsm)[i] = 0.f;

    const float* __restrict__ Wb = g_Wt2 + (size_t)hq * HID * 512;

    // packed bias / Wih-column pairs for this thread's 8 gate-columns
    unsigned long long bwp[4], wvp[4];
#pragma unroll
    for (int u2 = 0; u2 < 4; u2++) {
        bwp[u2] = pk2(g_bias2[hq * 512 + cx * 8 + u2 * 2],
                      g_bias2[hq * 512 + cx * 8 + u2 * 2 + 1]);
        wvp[u2] = pk2(g_wih2[hq * 512 + cx * 8 + u2 * 2],
                      g_wih2[hq * 512 + cx * 8 + u2 * 2 + 1]);
    }
    float cst[8][2];
#pragma unroll
    for (int ss = 0; ss < 8; ss++) { cst[ss][0] = 0.f; cst[ss][1] = 0.f; }
    __syncthreads();

    for (int t = 0; t < LSTEPS; t++) {
        if (tid < 64) {
            int n = n0 + tid;
            if (n > NSEQ - 1) n = NSEQ - 1;
            xs[tid] = g_xT[t * NSEQ + n];
        }
        __syncthreads();   // h stores (prev iter) + xs ready

        // acc2[ss][u2] = packed pair of gate pre-activations
        unsigned long long acc2[8][4];
#pragma unroll
        for (int ss = 0; ss < 8; ss++) {
            float xv = xs[sy * 8 + ss];
            unsigned long long xp = pk2(xv, xv);
#pragma unroll
            for (int u2 = 0; u2 < 4; u2++)
                acc2[ss][u2] = ffma2(xp, wvp[u2], bwp[u2]);
        }

#pragma unroll 2
        for (int k = 0; k < HID; k++) {
            const ulonglong2* wp =
                reinterpret_cast<const ulonglong2*>(Wb + k * 512 + cx * 8);
            ulonglong2 wA = wp[0];   // gate pairs 0-1, 2-3
            ulonglong2 wB = wp[1];   // gate pairs 4-5, 6-7
            float hv[8];
#pragma unroll
            for (int ss = 0; ss < 8; ss++) hv[ss] = hsm[sy * 8 + ss][k];
#pragma unroll
            for (int ss = 0; ss < 8; ss++) {
                unsigned long long hp = pk2(hv[ss], hv[ss]);
                acc2[ss][0] = ffma2(hp, wA.x, acc2[ss][0]);
                acc2[ss][1] = ffma2(hp, wA.y, acc2[ss][1]);
                acc2[ss][2] = ffma2(hp, wB.x, acc2[ss][2]);
                acc2[ss][3] = ffma2(hp, wB.y, acc2[ss][3]);
            }
        }
        __syncthreads();   // everyone done reading hsm/xs

        // gates: PyTorch order i,f,g,o  (row = g*128 + j; cidx = j*4 + g)
        // acc2[ss][0] = (zi, zf) of unit jj=0, acc2[ss][1] = (zg, zo) of jj=0
        // acc2[ss][2] = (zi, zf) of unit jj=1, acc2[ss][3] = (zg, zo) of jj=1
#pragma unroll
        for (int ss = 0; ss < 8; ss++) {
#pragma unroll
            for (int jj = 0; jj < 2; jj++) {
                float zi, zf, zg, zo;
                unpk2(acc2[ss][jj * 2 + 0], zi, zf);
                unpk2(acc2[ss][jj * 2 + 1], zg, zo);
                float cn = sigf(zf) * cst[ss][jj] + sigf(zi) * tanhf(zg);
                float hn = sigf(zo) * tanhf(cn);
                cst[ss][jj] = cn;
                hsm[sy * 8 + ss][cx * 2 + jj] = hn;
            }
        }
    }
    __syncthreads();

    if (hq < 8) {   // q: [h][n][d]
        for (int i = tid; i < 64 * HID; i += 512) {
            int s = i >> 7, d = i & 127;
            int n = n0 + s;
            if (n < NSEQ) g_q[((size_t)hq * NSEQ + n) * HID + d] = hsm[s][d];
        }
    } else {        // k: transposed [h][d][n]
        int h = hq - 8;
        for (int i = tid; i < 64 * HID; i += 512) {
            int d = i >> 6, s = i & 63;
            int n = n0 + s;
            if (n < NSEQ) g_kT[((size_t)h * HID + d) * NSEQ + n] = hsm[s][d];
        }
    }
}

// ---------------- fused attention: scores + leaky + mask + softmax + attn@v + leaky ----------------
// block: (h, b, 16-query tile), 256 threads
__global__ void k_attn(const float* __restrict__ graph, float* __restrict__ out) {
    int h = blockIdx.z, b = blockIdx.y, s0 = blockIdx.x * 16;
    int tid = threadIdx.x;
    __shared__ float qs[16][HID];     // 8 KB
    __shared__ float sc[16][328];     // 20.5 KB

    for (int i = tid; i < 16 * HID; i += 256) {
        int sq = i >> 7, d = i & 127;
        int s = s0 + sq;
        qs[sq][d] = (s < SLEN) ? g_q[((size_t)h * NSEQ + b * SLEN + s) * HID + d] : 0.f;
    }
    __syncthreads();

    // scores: each thread owns key positions t = tid, tid+256
    for (int t = tid; t < SLEN; t += 256) {
        float acc[16];
#pragma unroll
        for (int i = 0; i < 16; i++) acc[i] = 0.f;
        const float* kp = g_kT + (size_t)h * HID * NSEQ + b * SLEN + t;
        for (int d = 0; d < HID; d += 4) {
            float k0 = kp[(size_t)d * NSEQ];
            float k1 = kp[(size_t)(d + 1) * NSEQ];
            float k2 = kp[(size_t)(d + 2) * NSEQ];
            float k3 = kp[(size_t)(d + 3) * NSEQ];
#pragma unroll
            for (int sq = 0; sq < 16; sq++) {
                float4 q4 = *reinterpret_cast<const float4*>(&qs[sq][d]);
                acc[sq] += k0 * q4.x + k1 * q4.y + k2 * q4.z + k3 * q4.w;
            }
        }
#pragma unroll
        for (int sq = 0; sq < 16; sq++) {
            int s = s0 + sq;
            float v = acc[sq] * SCALE;
            v = v >= 0.f ? v : 0.2f * v;                     // leaky BEFORE mask
            bool keep = (s < SLEN) && ((s == t) || (graph[t * SLEN + s] != 0.f));
            sc[sq][t] = keep ? v : -1e9f;
        }
    }
    __syncthreads();

    // softmax per row: 16 lanes per row
    {
        int r = tid >> 4, ln = tid & 15;
        float mx = -3.4e38f;
        for (int i = ln; i < SLEN; i += 16) mx = fmaxf(mx, sc[r][i]);
#pragma unroll
        for (int o = 1; o < 16; o <<= 1) mx = fmaxf(mx, __shfl_xor_sync(0xffffffffu, mx, o));
        float sum = 0.f;
        for (int i = ln; i < SLEN; i += 16) {
            float e = __expf(sc[r][i] - mx);
            sc[r][i] = e;
            sum += e;
        }
#pragma unroll
        for (int o = 1; o < 16; o <<= 1) sum += __shfl_xor_sync(0xffffffffu, sum, o);
        float inv = 1.f / sum;
        for (int i = ln; i < SLEN; i += 16) sc[r][i] *= inv;
    }
    __syncthreads();

    // out = attn @ v, then leaky; thread: 4 queries x 3 output dims
    {
        int lg = tid & 63, sg = tid >> 6;
        float a2[4][3];
#pragma unroll
        for (int ss = 0; ss < 4; ss++) { a2[ss][0] = 0.f; a2[ss][1] = 0.f; a2[ss][2] = 0.f; }
        const float* vb = g_v + ((size_t)h * NSEQ + b * SLEN) * LSTEPS;
        for (int t = 0; t < SLEN; t++) {
            float a[4];
#pragma unroll
            for (int ss = 0; ss < 4; ss++) a[ss] = sc[sg * 4 + ss][t];
            const float* vr = vb + (size_t)t * LSTEPS + lg * 3;
            float v0 = vr[0], v1 = vr[1], v2 = vr[2];
#pragma unroll
            for (int ss = 0; ss < 4; ss++) {
                a2[ss][0] += a[ss] * v0;
                a2[ss][1] += a[ss] * v1;
                a2[ss][2] += a[ss] * v2;
            }
        }
#pragma unroll
        for (int ss = 0; ss < 4; ss++) {
            int s = s0 + sg * 4 + ss;
            if (s < SLEN) {
#pragma unroll
                for (int q = 0; q < 3; q++) {
                    float vv = a2[ss][q];
                    vv = vv >= 0.f ? vv : 0.2f * vv;        // final leaky
                    int l = lg * 3 + q;
                    out[(((size_t)(b * SLEN + s)) * LSTEPS + l) * NH + h] = vv;
                }
            }
        }
    }
}

// ---------------- launch ----------------
extern "C" void kernel_launch(void* const* d_in, const int* in_sizes, int n_in,
                              void* d_out, int out_size) {
    const float* x     = (const float*)d_in[0];
    const float* graph = (const float*)d_in[1];
    const float* qWih  = (const float*)d_in[2];
    const float* qWhh  = (const float*)d_in[3];
    const float* qbih  = (const float*)d_in[4];
    const float* qbhh  = (const float*)d_in[5];
    const float* kWih  = (const float*)d_in[6];
    const float* kWhh  = (const float*)d_in[7];
    const float* kbih  = (const float*)d_in[8];
    const float* kbhh  = (const float*)d_in[9];
    const float* vWih  = (const float*)d_in[10];
    const float* vWhh  = (const float*)d_in[11];
    const float* vbih  = (const float*)d_in[12];
    const float* vbhh  = (const float*)d_in[13];
    float* out = (float*)d_out;

    k_prep_x<<<(LSTEPS * NSEQ + 255) / 256, 256>>>(x);
    k_prep_w<<<(16 * HID * 512 + 255) / 256, 256>>>(qWih, qWhh, qbih, qbhh, kWih, kWhh, kbih, kbhh);
    k_v_lstm<<<(NH * NSEQ + 255) / 256, 256>>>(vWih, vWhh, vbih, vbhh);
    k_qk_lstm<<<dim3(163, 16, 1), 512>>>();
    k_attn<<<dim3(21, NB, NH), 256>>>(graph, out);
}

// round 8
// speedup vs baseline: 1.0716x; 1.0716x over previous
#include <cuda_runtime.h>

#define NSEQ   10400     // B*S = 32*325
#define LSTEPS 192       // L
#define HID    128       // D_MODEL
#define NH     8
#define SLEN   325
#define NB     32
#define SCALE  0.08838834764831845f  // 1/sqrt(128)

// ---------------- scratch (static device arrays; no allocation) ----------------
__device__ float g_xT[LSTEPS * NSEQ];          //  8 MB  x transposed [l][n]
__device__ float g_Wt2[16 * HID * 512];        //  4 MB  gate-interleaved W^T [hq][k][col]
__device__ float g_bias2[16 * 512];            //         bih+bhh, interleaved
__device__ float g_wih2[16 * 512];             //         Wih col, interleaved
__device__ float g_q[NH * NSEQ * HID];         // 43 MB  q final hidden [h][n][d]
__device__ float g_kT[NH * HID * NSEQ];        // 43 MB  k final hidden transposed [h][d][n]
__device__ float g_v[NH * NSEQ * LSTEPS];      // 64 MB  v full outputs [h][n][l]

__device__ __forceinline__ float sigf(float x) { return 1.f / (1.f + __expf(-x)); }

// ---- packed f32x2 helpers (FFMA2 path: 2x fp32 FMA throughput on sm_103a) ----
__device__ __forceinline__ unsigned long long pk2(float lo, float hi) {
    unsigned long long r;
    asm("mov.b64 %0, {%1, %2};" : "=l"(r) : "f"(lo), "f"(hi));
    return r;
}
__device__ __forceinline__ void unpk2(unsigned long long v, float& lo, float& hi) {
    asm("mov.b64 {%0, %1}, %2;" : "=f"(lo), "=f"(hi) : "l"(v));
}
__device__ __forceinline__ unsigned long long ffma2(unsigned long long a,
                                                    unsigned long long b,
                                                    unsigned long long c) {
    unsigned long long d;
    asm("fma.rn.f32x2 %0, %1, %2, %3;" : "=l"(d) : "l"(a), "l"(b), "l"(c));
    return d;
}

__device__ __forceinline__ void cpa16(void* dst_smem, const void* src) {
    unsigned s = (unsigned)__cvta_generic_to_shared(dst_smem);
    asm volatile("cp.async.cg.shared.global [%0], [%1], 16;" :: "r"(s), "l"(src));
}
__device__ __forceinline__ void cpa_commit() { asm volatile("cp.async.commit_group;"); }
__device__ __forceinline__ void cpa_wait1()  { asm volatile("cp.async.wait_group 1;"); }

// ---------------- prep: transpose x to [l][n] ----------------
__global__ void k_prep_x(const float* __restrict__ x) {
    int i = blockIdx.x * 256 + threadIdx.x;
    if (i < LSTEPS * NSEQ) {
        int l = i / NSEQ, n = i % NSEQ;
        g_xT[i] = x[(size_t)n * LSTEPS + l];
    }
}

// ---------------- prep: gate-interleaved transposed weights ----------------
// Wt2[hq][k][j*4+g] = Whh[h][g*128+j][k]   (hq<8: q-lstm head hq, else k-lstm head hq-8)
__global__ void k_prep_w(const float* __restrict__ qWih, const float* __restrict__ qWhh,
                         const float* __restrict__ qbih, const float* __restrict__ qbhh,
                         const float* __restrict__ kWih, const float* __restrict__ kWhh,
                         const float* __restrict__ kbih, const float* __restrict__ kbhh) {
    int idx = blockIdx.x * 256 + threadIdx.x;
    if (idx >= 16 * HID * 512) return;
    int hq   = idx / (HID * 512);
    int rem  = idx % (HID * 512);
    int k    = rem / 512;
    int cidx = rem % 512;
    int j = cidx >> 2, g = cidx & 3;
    int row = g * HID + j;
    int h = hq & 7;
    const float* Whh = (hq < 8) ? (qWhh + (size_t)h * 512 * HID) : (kWhh + (size_t)h * 512 * HID);
    g_Wt2[idx] = Whh[row * HID + k];
    if (k == 0) {
        const float* Wih = (hq < 8) ? qWih + h * 512 : kWih + h * 512;
        const float* bi  = (hq < 8) ? qbih + h * 512 : kbih + h * 512;
        const float* bh  = (hq < 8) ? qbhh + h * 512 : kbhh + h * 512;
        g_wih2[hq * 512 + cidx]  = Wih[row];
        g_bias2[hq * 512 + cidx] = bi[row] + bh[row];
    }
}

// ---------------- v LSTM: hidden size 1, one thread per (head, seq) ----------------
__global__ void k_v_lstm(const float* __restrict__ wih, const float* __restrict__ whh,
                         const float* __restrict__ bih, const float* __restrict__ bhh) {
    int idx = blockIdx.x * 256 + threadIdx.x;
    if (idx >= NH * NSEQ) return;
    int h = idx / NSEQ, n = idx % NSEQ;
    float wi[4], wh[4], bb[4];
#pragma unroll
    for (int g = 0; g < 4; g++) {
        wi[g] = wih[h * 4 + g];
        wh[g] = whh[h * 4 + g];
        bb[g] = bih[h * 4 + g] + bhh[h * 4 + g];
    }
    float hv = 0.f, cv = 0.f;
    float* vp = g_v + (size_t)idx * LSTEPS;
    for (int t = 0; t < LSTEPS; t++) {
        float xv = g_xT[t * NSEQ + n];
        float zi = wi[0] * xv + wh[0] * hv + bb[0];
        float zf = wi[1] * xv + wh[1] * hv + bb[1];
        float zg = wi[2] * xv + wh[2] * hv + bb[2];
        float zo = wi[3] * xv + wh[3] * hv + bb[3];
        cv = sigf(zf) * cv + sigf(zi) * tanhf(zg);
        hv = sigf(zo) * tanhf(cv);
        vp[t] = hv;
    }
}

// ---------------- q/k LSTM: persistent tile of 64 seqs, 512 threads ----------------
// Thread (cx = tid&63, sy = tid>>6): 8 seqs x 2 units (cx and 64+cx), 4 gates each.
// Weights staged via cp.async into 4 x 32KB smem chunks (depth-2 prefetch).
// h kept in smem transposed & duplicated: hsm2[k][seq] = (h,h) for direct FFMA2 operand.
// Dyn smem: wb 131072 B + hsm2 128*66*8 = 67584 B + xs 256 B = 198912 B.
#define CHK   16                       // k-rows per chunk
#define WBUFS 4
#define HP2   66                       // hsm2 pitch in ulonglong (8B) units

__global__ __launch_bounds__(512, 1) void k_qk_lstm() {
    extern __shared__ char smem[];
    float* wb = (float*)smem;                                        // [4][16][512]
    unsigned long long* hsm2 = (unsigned long long*)(smem + 131072); // [128][66]
    float* xs = (float*)(smem + 131072 + 67584);                     // [64]

    int hq = blockIdx.y;
    int n0 = blockIdx.x * 64;
    int tid = threadIdx.x;
    int cx = tid & 63, sy = tid >> 6;

    // zero h
    for (int i = tid; i < HID * HP2; i += 512) hsm2[i] = 0ull;

    const float* __restrict__ Wb = g_Wt2 + (size_t)hq * HID * 512;

    // this thread's 8 gate-columns: unit u0=cx -> cols cx*4..+3 ; unit u1=64+cx -> cols 256+cx*4..+3
    int ca = cx * 4, cb = 256 + cx * 4;
    unsigned long long bwp[4], wvp[4];
    bwp[0] = pk2(g_bias2[hq * 512 + ca],     g_bias2[hq * 512 + ca + 1]);
    bwp[1] = pk2(g_bias2[hq * 512 + ca + 2], g_bias2[hq * 512 + ca + 3]);
    bwp[2] = pk2(g_bias2[hq * 512 + cb],     g_bias2[hq * 512 + cb + 1]);
    bwp[3] = pk2(g_bias2[hq * 512 + cb + 2], g_bias2[hq * 512 + cb + 3]);
    wvp[0] = pk2(g_wih2[hq * 512 + ca],      g_wih2[hq * 512 + ca + 1]);
    wvp[1] = pk2(g_wih2[hq * 512 + ca + 2],  g_wih2[hq * 512 + ca + 3]);
    wvp[2] = pk2(g_wih2[hq * 512 + cb],      g_wih2[hq * 512 + cb + 1]);
    wvp[3] = pk2(g_wih2[hq * 512 + cb + 2],  g_wih2[hq * 512 + cb + 3]);

    float cst[8][2];
#pragma unroll
    for (int ss = 0; ss < 8; ss++) { cst[ss][0] = 0.f; cst[ss][1] = 0.f; }

    // prime chunks 0 and 1
#pragma unroll
    for (int pj = 0; pj < 2; pj++) {
        const float* src = Wb + (size_t)(pj & 7) * CHK * 512;
        float* dst = wb + (pj & 3) * CHK * 512;
#pragma unroll
        for (int m = 0; m < 4; m++) {
            int idx = m * 512 + tid;          // 16B unit index
            cpa16(dst + idx * 4, src + idx * 4);
        }
        cpa_commit();
    }
    __syncthreads();   // hsm2 zeros visible

    unsigned long long acc2[8][4];

    for (int t = 0; t < LSTEPS; t++) {
        if (tid < 64) {
            int n = n0 + tid;
            if (n > NSEQ - 1) n = NSEQ - 1;
            xs[tid] = g_xT[t * NSEQ + n];
        }

        for (int c = 0; c < 8; c++) {
            int j = t * 8 + c;
            cpa_wait1();
            __syncthreads();   // chunk j staged in all threads; (c==0) also orders xs + h stores

            // prefetch chunk j+2 (weights repeat every 8 chunks)
            {
                int nj = j + 2;
                const float* src = Wb + (size_t)(nj & 7) * CHK * 512;
                float* dst = wb + (nj & 3) * CHK * 512;
#pragma unroll
                for (int m = 0; m < 4; m++) {
                    int idx = m * 512 + tid;
                    cpa16(dst + idx * 4, src + idx * 4);
                }
                cpa_commit();
            }

            if (c == 0) {
#pragma unroll
                for (int ss = 0; ss < 8; ss++) {
                    float xv = xs[sy * 8 + ss];
                    unsigned long long xp = pk2(xv, xv);
#pragma unroll
                    for (int u2 = 0; u2 < 4; u2++)
                        acc2[ss][u2] = ffma2(xp, wvp[u2], bwp[u2]);
                }
            }

            const float* wchunk = wb + (j & 3) * CHK * 512;
            int kg0 = c * CHK;
#pragma unroll 2
            for (int kl = 0; kl < CHK; kl++) {
                const ulonglong2* wpA =
                    reinterpret_cast<const ulonglong2*>(wchunk + kl * 512 + ca);
                const ulonglong2* wpB =
                    reinterpret_cast<const ulonglong2*>(wchunk + kl * 512 + cb);
                ulonglong2 wA = *wpA;   // (i,f),(g,o) of unit u0
                ulonglong2 wB = *wpB;   // (i,f),(g,o) of unit u1

                const unsigned long long* hrow = hsm2 + (size_t)(kg0 + kl) * HP2 + sy * 8;
                ulonglong2 h01 = *reinterpret_cast<const ulonglong2*>(hrow + 0);
                ulonglong2 h23 = *reinterpret_cast<const ulonglong2*>(hrow + 2);
                ulonglong2 h45 = *reinterpret_cast<const ulonglong2*>(hrow + 4);
                ulonglong2 h67 = *reinterpret_cast<const ulonglong2*>(hrow + 6);
                unsigned long long hp[8] = {h01.x, h01.y, h23.x, h23.y,
                                            h45.x, h45.y, h67.x, h67.y};
#pragma unroll
                for (int ss = 0; ss < 8; ss++) {
                    acc2[ss][0] = ffma2(hp[ss], wA.x, acc2[ss][0]);
                    acc2[ss][1] = ffma2(hp[ss], wA.y, acc2[ss][1]);
                    acc2[ss][2] = ffma2(hp[ss], wB.x, acc2[ss][2]);
                    acc2[ss][3] = ffma2(hp[ss], wB.y, acc2[ss][3]);
                }
            }
        }
        __syncthreads();   // all reads of hsm2 done before rewriting

        // gates: pairs are (zi,zf),(zg,zo) per unit; PyTorch order i,f,g,o
        float hn0[8], hn1[8];
#pragma unroll
        for (int ss = 0; ss < 8; ss++) {
            float zi, zf, zg, zo;
            unpk2(acc2[ss][0], zi, zf);
            unpk2(acc2[ss][1], zg, zo);
            float cn = sigf(zf) * cst[ss][0] + sigf(zi) * tanhf(zg);
            hn0[ss] = sigf(zo) * tanhf(cn);
            cst[ss][0] = cn;
            unpk2(acc2[ss][2], zi, zf);
            unpk2(acc2[ss][3], zg, zo);
            cn = sigf(zf) * cst[ss][1] + sigf(zi) * tanhf(zg);
            hn1[ss] = sigf(zo) * tanhf(cn);
            cst[ss][1] = cn;
        }
        // store duplicated pairs: row u0=cx, row u1=64+cx, seqs sy*8..sy*8+7
        {
            float4* r0 = reinterpret_cast<float4*>(hsm2 + (size_t)cx * HP2 + sy * 8);
            float4* r1 = reinterpret_cast<float4*>(hsm2 + (size_t)(64 + cx) * HP2 + sy * 8);
#pragma unroll
            for (int m = 0; m < 4; m++) {
                r0[m] = make_float4(hn0[2 * m], hn0[2 * m], hn0[2 * m + 1], hn0[2 * m + 1]);
                r1[m] = make_float4(hn1[2 * m], hn1[2 * m], hn1[2 * m + 1], hn1[2 * m + 1]);
            }
        }
    }
    __syncthreads();

    if (hq < 8) {   // q: [h][n][d]
        for (int i = tid; i < 64 * HID; i += 512) {
            int s = i >> 7, d = i & 127;
            int n = n0 + s;
            if (n < NSEQ) {
                float hval = reinterpret_cast<float2*>(hsm2 + (size_t)d * HP2 + s)->x;
                g_q[((size_t)hq * NSEQ + n) * HID + d] = hval;
            }
        }
    } else {        // k: transposed [h][d][n]
        int h = hq - 8;
        for (int i = tid; i < 64 * HID; i += 512) {
            int d = i >> 6, s = i & 63;
            int n = n0 + s;
            if (n < NSEQ) {
                float hval = reinterpret_cast<float2*>(hsm2 + (size_t)d * HP2 + s)->x;
                g_kT[((size_t)h * HID + d) * NSEQ + n] = hval;
            }
        }
    }
}

// ---------------- fused attention: scores + leaky + mask + softmax + attn@v + leaky ----------------
// block: (h, b, 16-query tile), 256 threads
__global__ void k_attn(const float* __restrict__ graph, float* __restrict__ out) {
    int h = blockIdx.z, b = blockIdx.y, s0 = blockIdx.x * 16;
    int tid = threadIdx.x;
    __shared__ float qs[16][HID];     // 8 KB
    __shared__ float sc[16][328];     // 20.5 KB

    for (int i = tid; i < 16 * HID; i += 256) {
        int sq = i >> 7, d = i & 127;
        int s = s0 + sq;
        qs[sq][d] = (s < SLEN) ? g_q[((size_t)h * NSEQ + b * SLEN + s) * HID + d] : 0.f;
    }
    __syncthreads();

    // scores: each thread owns key positions t = tid, tid+256
    for (int t = tid; t < SLEN; t += 256) {
        float acc[16];
#pragma unroll
        for (int i = 0; i < 16; i++) acc[i] = 0.f;
        const float* kp = g_kT + (size_t)h * HID * NSEQ + b * SLEN + t;
        for (int d = 0; d < HID; d += 4) {
            float k0 = kp[(size_t)d * NSEQ];
            float k1 = kp[(size_t)(d + 1) * NSEQ];
            float k2 = kp[(size_t)(d + 2) * NSEQ];
            float k3 = kp[(size_t)(d + 3) * NSEQ];
#pragma unroll
            for (int sq = 0; sq < 16; sq++) {
                float4 q4 = *reinterpret_cast<const float4*>(&qs[sq][d]);
                acc[sq] += k0 * q4.x + k1 * q4.y + k2 * q4.z + k3 * q4.w;
            }
        }
#pragma unroll
        for (int sq = 0; sq < 16; sq++) {
            int s = s0 + sq;
            float v = acc[sq] * SCALE;
            v = v >= 0.f ? v : 0.2f * v;                     // leaky BEFORE mask
            bool keep = (s < SLEN) && ((s == t) || (graph[t * SLEN + s] != 0.f));
            sc[sq][t] = keep ? v : -1e9f;
        }
    }
    __syncthreads();

    // softmax per row: 16 lanes per row
    {
        int r = tid >> 4, ln = tid & 15;
        float mx = -3.4e38f;
        for (int i = ln; i < SLEN; i += 16) mx = fmaxf(mx, sc[r][i]);
#pragma unroll
        for (int o = 1; o < 16; o <<= 1) mx = fmaxf(mx, __shfl_xor_sync(0xffffffffu, mx, o));
        float sum = 0.f;
        for (int i = ln; i < SLEN; i += 16) {
            float e = __expf(sc[r][i] - mx);
            sc[r][i] = e;
            sum += e;
        }
#pragma unroll
        for (int o = 1; o < 16; o <<= 1) sum += __shfl_xor_sync(0xffffffffu, sum, o);
        float inv = 1.f / sum;
        for (int i = ln; i < SLEN; i += 16) sc[r][i] *= inv;
    }
    __syncthreads();

    // out = attn @ v, then leaky; thread: 4 queries x 3 output dims
    {
        int lg = tid & 63, sg = tid >> 6;
        float a2[4][3];
#pragma unroll
        for (int ss = 0; ss < 4; ss++) { a2[ss][0] = 0.f; a2[ss][1] = 0.f; a2[ss][2] = 0.f; }
        const float* vb = g_v + ((size_t)h * NSEQ + b * SLEN) * LSTEPS;
        for (int t = 0; t < SLEN; t++) {
            float a[4];
#pragma unroll
            for (int ss = 0; ss < 4; ss++) a[ss] = sc[sg * 4 + ss][t];
            const float* vr = vb + (size_t)t * LSTEPS + lg * 3;
            float v0 = vr[0], v1 = vr[1], v2 = vr[2];
#pragma unroll
            for (int ss = 0; ss < 4; ss++) {
                a2[ss][0] += a[ss] * v0;
                a2[ss][1] += a[ss] * v1;
                a2[ss][2] += a[ss] * v2;
            }
        }
#pragma unroll
        for (int ss = 0; ss < 4; ss++) {
            int s = s0 + sg * 4 + ss;
            if (s < SLEN) {
#pragma unroll
                for (int q = 0; q < 3; q++) {
                    float vv = a2[ss][q];
                    vv = vv >= 0.f ? vv : 0.2f * vv;        // final leaky
                    int l = lg * 3 + q;
                    out[(((size_t)(b * SLEN + s)) * LSTEPS + l) * NH + h] = vv;
                }
            }
        }
    }
}

// ---------------- launch ----------------
extern "C" void kernel_launch(void* const* d_in, const int* in_sizes, int n_in,
                              void* d_out, int out_size) {
    const float* x     = (const float*)d_in[0];
    const float* graph = (const float*)d_in[1];
    const float* qWih  = (const float*)d_in[2];
    const float* qWhh  = (const float*)d_in[3];
    const float* qbih  = (const float*)d_in[4];
    const float* qbhh  = (const float*)d_in[5];
    const float* kWih  = (const float*)d_in[6];
    const float* kWhh  = (const float*)d_in[7];
    const float* kbih  = (const float*)d_in[8];
    const float* kbhh  = (const float*)d_in[9];
    const float* vWih  = (const float*)d_in[10];
    const float* vWhh  = (const float*)d_in[11];
    const float* vbih  = (const float*)d_in[12];
    const float* vbhh  = (const float*)d_in[13];
    float* out = (float*)d_out;

    const int dynsmem = 131072 + 67584 + 256;   // 198912 B
    cudaFuncSetAttribute(k_qk_lstm, cudaFuncAttributeMaxDynamicSharedMemorySize, dynsmem);

    k_prep_x<<<(LSTEPS * NSEQ + 255) / 256, 256>>>(x);
    k_prep_w<<<(16 * HID * 512 + 255) / 256, 256>>>(qWih, qWhh, qbih, qbhh, kWih, kWhh, kbih, kbhh);
    k_v_lstm<<<(NH * NSEQ + 255) / 256, 256>>>(vWih, vWhh, vbih, vbhh);
    k_qk_lstm<<<dim3(163, 16, 1), 512, dynsmem>>>();
    k_attn<<<dim3(21, NB, NH), 256>>>(graph, out);
}

// round 10
// speedup vs baseline: 5.8244x; 5.4350x over previous
#include <cuda_runtime.h>
#include <cuda_fp16.h>
#include <cstdint>

#define NSEQ   10400     // B*S = 32*325
#define LSTEPS 192       // L
#define HID    128       // D_MODEL
#define NH     8
#define SLEN   325
#define NB     32
#define SCALE  0.08838834764831845f  // 1/sqrt(128)

// ---------------- scratch (static device arrays; no allocation) ----------------
__device__ float g_xT[LSTEPS * NSEQ];                    //  8 MB  x transposed [l][n]
__device__ __align__(16) __half g_Wh16[16 * 512 * HID];  //  2 MB  swizzled fp16 W tiles
__device__ float g_bias2[16 * 512];                      //  bih+bhh by col n
__device__ float g_wih2[16 * 512];                       //  Wih by col n
__device__ float g_q[NH * NSEQ * HID];                   // 43 MB  q final hidden [h][n][d]
__device__ float g_kT[NH * HID * NSEQ];                  // 43 MB  k final hidden [h][d][n]
__device__ float g_v[NH * NSEQ * LSTEPS];                // 64 MB  v outputs [h][n][l]

__device__ __forceinline__ float sigf(float x) {
    return __fdividef(1.f, 1.f + __expf(-x));
}
__device__ __forceinline__ float tanhfast(float x) {
    return __fdividef(2.f, 1.f + __expf(-2.f * x)) - 1.f;
}

__device__ __forceinline__ void cpa16(void* dst_smem, const void* src) {
    unsigned s = (unsigned)__cvta_generic_to_shared(dst_smem);
    asm volatile("cp.async.cg.shared.global [%0], [%1], 16;" :: "r"(s), "l"(src));
}

__device__ __forceinline__ void ldsm4(uint32_t* r, uint32_t addr) {
    asm volatile("ldmatrix.sync.aligned.m8n8.x4.shared.b16 {%0,%1,%2,%3}, [%4];"
                 : "=r"(r[0]), "=r"(r[1]), "=r"(r[2]), "=r"(r[3]) : "r"(addr));
}

__device__ __forceinline__ void mma16816(float* c, const uint32_t* a, const uint32_t* b) {
    asm volatile(
        "mma.sync.aligned.m16n8k16.row.col.f32.f16.f16.f32 "
        "{%0,%1,%2,%3}, {%4,%5,%6,%7}, {%8,%9}, {%0,%1,%2,%3};"
        : "+f"(c[0]), "+f"(c[1]), "+f"(c[2]), "+f"(c[3])
        : "r"(a[0]), "r"(a[1]), "r"(a[2]), "r"(a[3]), "r"(b[0]), "r"(b[1]));
}

// ---------------- prep: transpose x to [l][n] ----------------
__global__ void k_prep_x(const float* __restrict__ x) {
    int i = blockIdx.x * 256 + threadIdx.x;
    if (i < LSTEPS * NSEQ) {
        int l = i / NSEQ, n = i % NSEQ;
        g_xT[i] = x[(size_t)n * LSTEPS + l];
    }
}

// ---------------- prep: fp16 weights in mma col layout, XOR-swizzled ----------------
// col n of unit j, gate g (PyTorch order i,f,g,o): n = (g>>1)*256 + 2j + (g&1).
// B tile per hq: [n=512][k=128] fp16, row = 256 B, byte off = n*256 + ((2k)^((n&7)<<4)).
__global__ void k_prep_w16(const float* __restrict__ qWih, const float* __restrict__ qWhh,
                           const float* __restrict__ qbih, const float* __restrict__ qbhh,
                           const float* __restrict__ kWih, const float* __restrict__ kWhh,
                           const float* __restrict__ kbih, const float* __restrict__ kbhh) {
    int idx = blockIdx.x * 256 + threadIdx.x;
    if (idx >= 16 * 512 * HID) return;
    int hq = idx >> 16;
    int n  = (idx >> 7) & 511;
    int k  = idx & 127;
    int j = (n & 255) >> 1;
    int g = ((n >> 8) << 1) | (n & 1);
    int row = g * HID + j;
    int h = hq & 7;
    const float* Whh = (hq < 8) ? (qWhh + (size_t)h * 512 * HID)
                                : (kWhh + (size_t)h * 512 * HID);
    float val = Whh[row * HID + k];
    int off = n * 256 + ((2 * k) ^ ((n & 7) << 4));
    *(__half*)((char*)g_Wh16 + (size_t)hq * 131072 + off) = __float2half(val);
    if (k == 0) {
        const float* Wih = (hq < 8) ? qWih + h * 512 : kWih + h * 512;
        const float* bi  = (hq < 8) ? qbih + h * 512 : kbih + h * 512;
        const float* bh  = (hq < 8) ? qbhh + h * 512 : kbhh + h * 512;
        g_wih2[hq * 512 + n]  = Wih[row];
        g_bias2[hq * 512 + n] = bi[row] + bh[row];
    }
}

// ---------------- v LSTM: hidden size 1, one thread per (head, seq) ----------------
__global__ void k_v_lstm(const float* __restrict__ wih, const float* __restrict__ whh,
                         const float* __restrict__ bih, const float* __restrict__ bhh) {
    int idx = blockIdx.x * 256 + threadIdx.x;
    if (idx >= NH * NSEQ) return;
    int h = idx / NSEQ, n = idx % NSEQ;
    float wi[4], wh[4], bb[4];
#pragma unroll
    for (int g = 0; g < 4; g++) {
        wi[g] = wih[h * 4 + g];
        wh[g] = whh[h * 4 + g];
        bb[g] = bih[h * 4 + g] + bhh[h * 4 + g];
    }
    float hv = 0.f, cv = 0.f;
    float* vp = g_v + (size_t)idx * LSTEPS;
    for (int t = 0; t < LSTEPS; t++) {
        float xv = g_xT[t * NSEQ + n];
        float zi = wi[0] * xv + wh[0] * hv + bb[0];
        float zf = wi[1] * xv + wh[1] * hv + bb[1];
        float zg = wi[2] * xv + wh[2] * hv + bb[2];
        float zo = wi[3] * xv + wh[3] * hv + bb[3];
        cv = sigf(zf) * cv + sigf(zi) * tanhf(zg);
        hv = sigf(zo) * tanhf(cv);
        vp[t] = hv;
    }
}

// ---------------- q/k LSTM via mma.sync (HMMA) ----------------
// CTA = (hq, 32-seq tile), 512 threads = 16 warps = 2 seq-bands x 8 col-groups.
// Z[32,512] = h[32,128]fp16 @ W^T[512,128]fp16 with fp32 accum in registers.
// Col layout: (zi,zf) of unit j at cols 2j,2j+1; (zg,zo) at 256+2j,257+2j ->
// each thread's mma fragments hold all 4 gates of its units. c fp32 in regs.
#define SM_B    0          // 131072 B
#define SM_A    131072     // 8192 B  h fp16 [32 rows x 256B]
#define SM_BIAS 139264     // 2048 B
#define SM_WIH  141312     // 2048 B
#define SM_XS   143360     // 128 B
#define SM_TOT  143488

__global__ __launch_bounds__(512, 1) void k_qk_mma() {
    extern __shared__ char smem[];
    const int hq  = blockIdx.y;
    const int n0  = blockIdx.x * 32;
    const int tid = threadIdx.x;
    const int wid = tid >> 5, lane = tid & 31;
    const int sb  = wid >> 3;          // seq band (16 seqs)
    const int cg  = wid & 7;           // col group (16 units)
    const int s0  = sb * 16;

    uint32_t smB = (uint32_t)__cvta_generic_to_shared(smem);
    uint32_t smA = smB + SM_A;
    float* biassm = (float*)(smem + SM_BIAS);
    float* wihsm  = (float*)(smem + SM_WIH);
    float* xs     = (float*)(smem + SM_XS);

    // stage B / bias / wih
    {
        const char* wsrc = (const char*)g_Wh16 + (size_t)hq * 131072;
        for (int i = tid; i < 8192; i += 512) cpa16(smem + SM_B + i * 16, wsrc + i * 16);
        if (tid < 128)
            cpa16(smem + SM_BIAS + tid * 16, (const char*)(g_bias2 + hq * 512) + tid * 16);
        else if (tid < 256)
            cpa16(smem + SM_WIH + (tid - 128) * 16,
                  (const char*)(g_wih2 + hq * 512) + (tid - 128) * 16);
        asm volatile("cp.async.commit_group;");
    }
    for (int i = tid; i < 2048; i += 512) ((uint32_t*)(smem + SM_A))[i] = 0u;  // h0 = 0
    asm volatile("cp.async.wait_group 0;");
    __syncthreads();

    // preload bias/wih: units u[ug][nt] = cg*16 + ug*8 + nt*4 + (lane&3)
    float bi_r[2][2][4], wi_r[2][2][4];
#pragma unroll
    for (int ug = 0; ug < 2; ug++)
#pragma unroll
        for (int nt = 0; nt < 2; nt++) {
            int u = cg * 16 + ug * 8 + nt * 4 + (lane & 3);
            bi_r[ug][nt][0] = biassm[2 * u];
            bi_r[ug][nt][1] = biassm[2 * u + 1];
            bi_r[ug][nt][2] = biassm[256 + 2 * u];
            bi_r[ug][nt][3] = biassm[257 + 2 * u];
            wi_r[ug][nt][0] = wihsm[2 * u];
            wi_r[ug][nt][1] = wihsm[2 * u + 1];
            wi_r[ug][nt][2] = wihsm[256 + 2 * u];
            wi_r[ug][nt][3] = wihsm[257 + 2 * u];
        }

    float cst[2][4];
#pragma unroll
    for (int a = 0; a < 2; a++)
#pragma unroll
        for (int b = 0; b < 4; b++) cst[a][b] = 0.f;

    // ldmatrix lane geometry
    const int arow = s0 + (lane & 7) + ((lane >> 3) & 1) * 8;
    const uint32_t a_rowbase = smA + arow * 256;
    const uint32_t a_xr = (arow & 7) << 4;
    const uint32_t a_kd = (lane >> 4) * 16;

    const int dlB = (lane & 7) + (lane >> 4) * 8;
    const uint32_t b_kd = ((lane >> 3) & 1) * 16;
    const uint32_t b_xr = (dlB & 7) << 4;
    const uint32_t b_rowbase = smB + (cg * 32 + dlB) * 256;

    const int rlo = s0 + (lane >> 2), rhi = rlo + 8;

    for (int t = 0; t < LSTEPS; t++) {
        if (tid < 32) xs[tid] = g_xT[t * NSEQ + n0 + tid];

        uint32_t afr[8][4];
#pragma unroll
        for (int ks = 0; ks < 8; ks++)
            ldsm4(afr[ks], a_rowbase + (((uint32_t)(ks * 32) + a_kd) ^ a_xr));

        __syncthreads();   // all A reads done; xs visible

        const float xlo = xs[rlo];
        const float xhi = xs[rhi];
        const bool last = (t == LSTEPS - 1);

#pragma unroll
        for (int ug = 0; ug < 2; ug++) {
            float acc[16];
#pragma unroll
            for (int i = 0; i < 16; i++) acc[i] = 0.f;
            uint32_t bb = b_rowbase + ug * 4096;
#pragma unroll
            for (int ks = 0; ks < 8; ks++) {
                uint32_t b0[4], b1[4];
                uint32_t ko = ((uint32_t)(ks * 32) + b_kd) ^ b_xr;
                ldsm4(b0, bb + ko);            // (zi,zf) ntiles
                ldsm4(b1, bb + 65536 + ko);    // (zg,zo) ntiles
                mma16816(acc + 0,  afr[ks], b0 + 0);
                mma16816(acc + 4,  afr[ks], b0 + 2);
                mma16816(acc + 8,  afr[ks], b1 + 0);
                mma16816(acc + 12, afr[ks], b1 + 2);
            }
            // epilogue: 4 cells = {lo,hi} x {ua, ub}
#pragma unroll
            for (int cell = 0; cell < 4; cell++) {
                int nt = cell >> 1, hi = cell & 1;
                float xv  = hi ? xhi : xlo;
                int   row = hi ? rhi : rlo;
                float zi = acc[cell * 2]     + bi_r[ug][nt][0] + wi_r[ug][nt][0] * xv;
                float zf = acc[cell * 2 + 1] + bi_r[ug][nt][1] + wi_r[ug][nt][1] * xv;
                float zg = acc[8 + cell * 2] + bi_r[ug][nt][2] + wi_r[ug][nt][2] * xv;
                float zo = acc[9 + cell * 2] + bi_r[ug][nt][3] + wi_r[ug][nt][3] * xv;
                float cp = cst[ug][cell];
                float cn = sigf(zf) * cp + sigf(zi) * tanhfast(zg);
                float hn = sigf(zo) * tanhfast(cn);
                cst[ug][cell] = cn;
                int u = cg * 16 + ug * 8 + nt * 4 + (lane & 3);
                if (!last) {
                    uint32_t addr = smA + row * 256 + (((uint32_t)(2 * u)) ^ ((row & 7) << 4));
                    __half hh = __float2half(hn);
                    asm volatile("st.shared.b16 [%0], %1;"
                                 :: "r"(addr), "h"(*(unsigned short*)&hh));
                } else {
                    int ng = n0 + row;
                    if (hq < 8) g_q[((size_t)hq * NSEQ + ng) * HID + u] = hn;
                    else        g_kT[((size_t)(hq - 8) * HID + u) * NSEQ + ng] = hn;
                }
            }
        }
        __syncthreads();   // h stores visible before next step's ldmatrix
    }
}

// ---------------- fused attention: scores + leaky + mask + softmax + attn@v + leaky ----------------
__global__ void k_attn(const float* __restrict__ graph, float* __restrict__ out) {
    int h = blockIdx.z, b = blockIdx.y, s0 = blockIdx.x * 16;
    int tid = threadIdx.x;
    __shared__ float qs[16][HID];
    __shared__ float sc[16][328];

    for (int i = tid; i < 16 * HID; i += 256) {
        int sq = i >> 7, d = i & 127;
        int s = s0 + sq;
        qs[sq][d] = (s < SLEN) ? g_q[((size_t)h * NSEQ + b * SLEN + s) * HID + d] : 0.f;
    }
    __syncthreads();

    for (int t = tid; t < SLEN; t += 256) {
        float acc[16];
#pragma unroll
        for (int i = 0; i < 16; i++) acc[i] = 0.f;
        const float* kp = g_kT + (size_t)h * HID * NSEQ + b * SLEN + t;
        for (int d = 0; d < HID; d += 4) {
            float k0 = kp[(size_t)d * NSEQ];
            float k1 = kp[(size_t)(d + 1) * NSEQ];
            float k2 = kp[(size_t)(d + 2) * NSEQ];
            float k3 = kp[(size_t)(d + 3) * NSEQ];
#pragma unroll
            for (int sq = 0; sq < 16; sq++) {
                float4 q4 = *reinterpret_cast<const float4*>(&qs[sq][d]);
                acc[sq] += k0 * q4.x + k1 * q4.y + k2 * q4.z + k3 * q4.w;
            }
        }
#pragma unroll
        for (int sq = 0; sq < 16; sq++) {
            int s = s0 + sq;
            float v = acc[sq] * SCALE;
            v = v >= 0.f ? v : 0.2f * v;
            bool keep = (s < SLEN) && ((s == t) || (graph[t * SLEN + s] != 0.f));
            sc[sq][t] = keep ? v : -1e9f;
        }
    }
    __syncthreads();

    {
        int r = tid >> 4, ln = tid & 15;
        float mx = -3.4e38f;
        for (int i = ln; i < SLEN; i += 16) mx = fmaxf(mx, sc[r][i]);
#pragma unroll
        for (int o = 1; o < 16; o <<= 1) mx = fmaxf(mx, __shfl_xor_sync(0xffffffffu, mx, o));
        float sum = 0.f;
        for (int i = ln; i < SLEN; i += 16) {
            float e = __expf(sc[r][i] - mx);
            sc[r][i] = e;
            sum += e;
        }
#pragma unroll
        for (int o = 1; o < 16; o <<= 1) sum += __shfl_xor_sync(0xffffffffu, sum, o);
        float inv = 1.f / sum;
        for (int i = ln; i < SLEN; i += 16) sc[r][i] *= inv;
    }
    __syncthreads();

    {
        int lg = tid & 63, sg = tid >> 6;
        float a2[4][3];
#pragma unroll
        for (int ss = 0; ss < 4; ss++) { a2[ss][0] = 0.f; a2[ss][1] = 0.f; a2[ss][2] = 0.f; }
        const float* vb = g_v + ((size_t)h * NSEQ + b * SLEN) * LSTEPS;
        for (int t = 0; t < SLEN; t++) {
            float a[4];
#pragma unroll
            for (int ss = 0; ss < 4; ss++) a[ss] = sc[sg * 4 + ss][t];
            const float* vr = vb + (size_t)t * LSTEPS + lg * 3;
            float v0 = vr[0], v1 = vr[1], v2 = vr[2];
#pragma unroll
            for (int ss = 0; ss < 4; ss++) {
                a2[ss][0] += a[ss] * v0;
                a2[ss][1] += a[ss] * v1;
                a2[ss][2] += a[ss] * v2;
            }
        }
#pragma unroll
        for (int ss = 0; ss < 4; ss++) {
            int s = s0 + sg * 4 + ss;
            if (s < SLEN) {
#pragma unroll
                for (int q = 0; q < 3; q++) {
                    float vv = a2[ss][q];
                    vv = vv >= 0.f ? vv : 0.2f * vv;
                    int l = lg * 3 + q;
                    out[(((size_t)(b * SLEN + s)) * LSTEPS + l) * NH + h] = vv;
                }
            }
        }
    }
}

// ---------------- launch ----------------
extern "C" void kernel_launch(void* const* d_in, const int* in_sizes, int n_in,
                              void* d_out, int out_size) {
    const float* x     = (const float*)d_in[0];
    const float* graph = (const float*)d_in[1];
    const float* qWih  = (const float*)d_in[2];
    const float* qWhh  = (const float*)d_in[3];
    const float* qbih  = (const float*)d_in[4];
    const float* qbhh  = (const float*)d_in[5];
    const float* kWih  = (const float*)d_in[6];
    const float* kWhh  = (const float*)d_in[7];
    const float* kbih  = (const float*)d_in[8];
    const float* kbhh  = (const float*)d_in[9];
    const float* vWih  = (const float*)d_in[10];
    const float* vWhh  = (const float*)d_in[11];
    const float* vbih  = (const float*)d_in[12];
    const float* vbhh  = (const float*)d_in[13];
    float* out = (float*)d_out;

    cudaFuncSetAttribute(k_qk_mma, cudaFuncAttributeMaxDynamicSharedMemorySize, SM_TOT);

    k_prep_x<<<(LSTEPS * NSEQ + 255) / 256, 256>>>(x);
    k_prep_w16<<<(16 * 512 * HID + 255) / 256, 256>>>(qWih, qWhh, qbih, qbhh,
                                                      kWih, kWhh, kbih, kbhh);
    k_v_lstm<<<(NH * NSEQ + 255) / 256, 256>>>(vWih, vWhh, vbih, vbhh);
    k_qk_mma<<<dim3(325, 16, 1), 512, SM_TOT>>>();
    k_attn<<<dim3(21, NB, NH), 256>>>(graph, out);
}

// round 11
// speedup vs baseline: 8.9185x; 1.5312x over previous
#include <cuda_runtime.h>
#include <cuda_fp16.h>
#include <cstdint>

#define NSEQ   10400     // B*S = 32*325
#define LSTEPS 192       // L
#define HID    128       // D_MODEL
#define NH     8
#define SLEN   325
#define NB     32
#define SCALE  0.08838834764831845f  // 1/sqrt(128)

// ---------------- scratch (static device arrays; no allocation) ----------------
__device__ float g_xT[LSTEPS * NSEQ];                    //  8 MB  x transposed [l][n]
__device__ __align__(16) __half g_Wh16[16 * 512 * HID];  //  2 MB  swizzled fp16 W tiles
__device__ float g_bias2[16 * 512];                      //  bih+bhh by col n
__device__ float g_wih2[16 * 512];                       //  Wih by col n
__device__ float g_q[NH * NSEQ * HID];                   // 43 MB  q final hidden [h][n][d]
__device__ float g_kT[NH * HID * NSEQ];                  // 43 MB  k final hidden [h][d][n]
__device__ float g_v[NH * NSEQ * LSTEPS];                // 64 MB  v outputs [h][n][l]

__device__ __forceinline__ float sigf(float x) {
    return __fdividef(1.f, 1.f + __expf(-x));
}

// MUFU.TANH fast paths (1 MUFU each)
__device__ __forceinline__ float tanha(float x) {
    float y;
    asm("tanh.approx.f32 %0, %1;" : "=f"(y) : "f"(x));
    return y;
}
__device__ __forceinline__ float siga(float x) {
    return fmaf(0.5f, tanha(0.5f * x), 0.5f);
}

__device__ __forceinline__ void cpa16(void* dst_smem, const void* src) {
    unsigned s = (unsigned)__cvta_generic_to_shared(dst_smem);
    asm volatile("cp.async.cg.shared.global [%0], [%1], 16;" :: "r"(s), "l"(src));
}

__device__ __forceinline__ void ldsm4(uint32_t* r, uint32_t addr) {
    asm volatile("ldmatrix.sync.aligned.m8n8.x4.shared.b16 {%0,%1,%2,%3}, [%4];"
                 : "=r"(r[0]), "=r"(r[1]), "=r"(r[2]), "=r"(r[3]) : "r"(addr));
}

__device__ __forceinline__ void mma16816(float* c, const uint32_t* a, const uint32_t* b) {
    asm volatile(
        "mma.sync.aligned.m16n8k16.row.col.f32.f16.f16.f32 "
        "{%0,%1,%2,%3}, {%4,%5,%6,%7}, {%8,%9}, {%0,%1,%2,%3};"
        : "+f"(c[0]), "+f"(c[1]), "+f"(c[2]), "+f"(c[3])
        : "r"(a[0]), "r"(a[1]), "r"(a[2]), "r"(a[3]), "r"(b[0]), "r"(b[1]));
}

// ---------------- prep: transpose x to [l][n] ----------------
__global__ void k_prep_x(const float* __restrict__ x) {
    int i = blockIdx.x * 256 + threadIdx.x;
    if (i < LSTEPS * NSEQ) {
        int l = i / NSEQ, n = i % NSEQ;
        g_xT[i] = x[(size_t)n * LSTEPS + l];
    }
}

// ---------------- prep: fp16 weights in mma col layout, XOR-swizzled ----------------
// col n of unit j, gate g (PyTorch order i,f,g,o): n = (g>>1)*256 + 2j + (g&1).
// B tile per hq: [n=512][k=128] fp16, row = 256 B, byte off = n*256 + ((2k)^((n&7)<<4)).
__global__ void k_prep_w16(const float* __restrict__ qWih, const float* __restrict__ qWhh,
                           const float* __restrict__ qbih, const float* __restrict__ qbhh,
                           const float* __restrict__ kWih, const float* __restrict__ kWhh,
                           const float* __restrict__ kbih, const float* __restrict__ kbhh) {
    int idx = blockIdx.x * 256 + threadIdx.x;
    if (idx >= 16 * 512 * HID) return;
    int hq = idx >> 16;
    int n  = (idx >> 7) & 511;
    int k  = idx & 127;
    int j = (n & 255) >> 1;
    int g = ((n >> 8) << 1) | (n & 1);
    int row = g * HID + j;
    int h = hq & 7;
    const float* Whh = (hq < 8) ? (qWhh + (size_t)h * 512 * HID)
                                : (kWhh + (size_t)h * 512 * HID);
    float val = Whh[row * HID + k];
    int off = n * 256 + ((2 * k) ^ ((n & 7) << 4));
    *(__half*)((char*)g_Wh16 + (size_t)hq * 131072 + off) = __float2half(val);
    if (k == 0) {
        const float* Wih = (hq < 8) ? qWih + h * 512 : kWih + h * 512;
        const float* bi  = (hq < 8) ? qbih + h * 512 : kbih + h * 512;
        const float* bh  = (hq < 8) ? qbhh + h * 512 : kbhh + h * 512;
        g_wih2[hq * 512 + n]  = Wih[row];
        g_bias2[hq * 512 + n] = bi[row] + bh[row];
    }
}

// ---------------- v LSTM: hidden size 1, one thread per (head, seq) ----------------
__global__ void k_v_lstm(const float* __restrict__ wih, const float* __restrict__ whh,
                         const float* __restrict__ bih, const float* __restrict__ bhh) {
    int idx = blockIdx.x * 256 + threadIdx.x;
    if (idx >= NH * NSEQ) return;
    int h = idx / NSEQ, n = idx % NSEQ;
    float wi[4], wh[4], bb[4];
#pragma unroll
    for (int g = 0; g < 4; g++) {
        wi[g] = wih[h * 4 + g];
        wh[g] = whh[h * 4 + g];
        bb[g] = bih[h * 4 + g] + bhh[h * 4 + g];
    }
    float hv = 0.f, cv = 0.f;
    float* vp = g_v + (size_t)idx * LSTEPS;
    for (int t = 0; t < LSTEPS; t++) {
        float xv = g_xT[t * NSEQ + n];
        float zi = wi[0] * xv + wh[0] * hv + bb[0];
        float zf = wi[1] * xv + wh[1] * hv + bb[1];
        float zg = wi[2] * xv + wh[2] * hv + bb[2];
        float zo = wi[3] * xv + wh[3] * hv + bb[3];
        cv = sigf(zf) * cv + sigf(zi) * tanhf(zg);
        hv = sigf(zo) * tanhf(cv);
        vp[t] = hv;
    }
}

// ---------------- q/k LSTM via mma.sync (HMMA) ----------------
// CTA = (hq, 32-seq tile), 512 threads = 16 warps = 2 seq-bands x 8 col-groups.
// The two 16-seq bands are fully independent (band-private A rows, read-only B)
// -> band-private named barriers. A tile double-buffered -> 1 barrier per step.
// Gates via MUFU.TANH (tanh.approx; sigmoid = 0.5*tanh(x/2)+0.5). c fp32 in regs.
#define SM_B    0          // 131072 B
#define SM_A    131072     // 16384 B  h fp16, 2 bufs x [32 rows x 256B]
#define SM_BIAS 147456     // 2048 B
#define SM_WIH  149504     // 2048 B
#define SM_TOT  151552

__global__ __launch_bounds__(512, 1) void k_qk_mma() {
    extern __shared__ char smem[];
    const int hq  = blockIdx.y;
    const int n0  = blockIdx.x * 32;
    const int tid = threadIdx.x;
    const int wid = tid >> 5, lane = tid & 31;
    const int sb  = wid >> 3;          // seq band (16 seqs)
    const int cg  = wid & 7;           // col group (16 units)
    const int s0  = sb * 16;

    uint32_t smB = (uint32_t)__cvta_generic_to_shared(smem);
    uint32_t smA = smB + SM_A;
    float* biassm = (float*)(smem + SM_BIAS);
    float* wihsm  = (float*)(smem + SM_WIH);

    // stage B / bias / wih
    {
        const char* wsrc = (const char*)g_Wh16 + (size_t)hq * 131072;
        for (int i = tid; i < 8192; i += 512) cpa16(smem + SM_B + i * 16, wsrc + i * 16);
        if (tid < 128)
            cpa16(smem + SM_BIAS + tid * 16, (const char*)(g_bias2 + hq * 512) + tid * 16);
        else if (tid < 256)
            cpa16(smem + SM_WIH + (tid - 128) * 16,
                  (const char*)(g_wih2 + hq * 512) + (tid - 128) * 16);
        asm volatile("cp.async.commit_group;");
    }
    for (int i = tid; i < 2048; i += 512) ((uint32_t*)(smem + SM_A))[i] = 0u;  // h0=0 buf0
    asm volatile("cp.async.wait_group 0;");
    __syncthreads();

    // preload bias/wih: units u[ug][nt] = cg*16 + ug*8 + nt*4 + (lane&3)
    float bi_r[2][2][4], wi_r[2][2][4];
#pragma unroll
    for (int ug = 0; ug < 2; ug++)
#pragma unroll
        for (int nt = 0; nt < 2; nt++) {
            int u = cg * 16 + ug * 8 + nt * 4 + (lane & 3);
            bi_r[ug][nt][0] = biassm[2 * u];
            bi_r[ug][nt][1] = biassm[2 * u + 1];
            bi_r[ug][nt][2] = biassm[256 + 2 * u];
            bi_r[ug][nt][3] = biassm[257 + 2 * u];
            wi_r[ug][nt][0] = wihsm[2 * u];
            wi_r[ug][nt][1] = wihsm[2 * u + 1];
            wi_r[ug][nt][2] = wihsm[256 + 2 * u];
            wi_r[ug][nt][3] = wihsm[257 + 2 * u];
        }

    float cst[2][4];
#pragma unroll
    for (int a = 0; a < 2; a++)
#pragma unroll
        for (int b = 0; b < 4; b++) cst[a][b] = 0.f;

    // ldmatrix lane geometry (identical to R10)
    const int arow = s0 + (lane & 7) + ((lane >> 3) & 1) * 8;
    const uint32_t a_rowoff = arow * 256;
    const uint32_t a_xr = (arow & 7) << 4;
    const uint32_t a_kd = (lane >> 4) * 16;

    const int dlB = (lane & 7) + (lane >> 4) * 8;
    const uint32_t b_kd = ((lane >> 3) & 1) * 16;
    const uint32_t b_xr = (dlB & 7) << 4;
    const uint32_t b_rowbase = smB + (cg * 32 + dlB) * 256;

    const int rlo = s0 + (lane >> 2), rhi = rlo + 8;
    const float* xlo_p = g_xT + n0 + rlo;
    const float* xhi_p = g_xT + n0 + rhi;

    const int bar_id = sb + 1;   // band-private named barrier

    for (int t = 0; t < LSTEPS; t++) {
        const uint32_t rbuf = smA + ((t & 1) ? 8192u : 0u);
        const uint32_t wbuf = smA + ((t & 1) ? 0u : 8192u);

        // per-thread x loads (1 L1 line per step per CTA)
        const float xlo = xlo_p[t * NSEQ];
        const float xhi = xhi_p[t * NSEQ];

        uint32_t afr[8][4];
#pragma unroll
        for (int ks = 0; ks < 8; ks++)
            ldsm4(afr[ks], rbuf + a_rowoff + (((uint32_t)(ks * 32) + a_kd) ^ a_xr));

        const bool last = (t == LSTEPS - 1);

#pragma unroll
        for (int ug = 0; ug < 2; ug++) {
            float acc[16];
#pragma unroll
            for (int i = 0; i < 16; i++) acc[i] = 0.f;
            uint32_t bb = b_rowbase + ug * 4096;
#pragma unroll
            for (int ks = 0; ks < 8; ks++) {
                uint32_t b0[4], b1[4];
                uint32_t ko = ((uint32_t)(ks * 32) + b_kd) ^ b_xr;
                ldsm4(b0, bb + ko);            // (zi,zf) ntiles
                ldsm4(b1, bb + 65536 + ko);    // (zg,zo) ntiles
                mma16816(acc + 0,  afr[ks], b0 + 0);
                mma16816(acc + 4,  afr[ks], b0 + 2);
                mma16816(acc + 8,  afr[ks], b1 + 0);
                mma16816(acc + 12, afr[ks], b1 + 2);
            }
            // epilogue: 4 cells = {lo,hi} x {ua, ub}
#pragma unroll
            for (int cell = 0; cell < 4; cell++) {
                int nt = cell >> 1, hi = cell & 1;
                float xv  = hi ? xhi : xlo;
                int   row = hi ? rhi : rlo;
                float zi = acc[cell * 2]     + bi_r[ug][nt][0] + wi_r[ug][nt][0] * xv;
                float zf = acc[cell * 2 + 1] + bi_r[ug][nt][1] + wi_r[ug][nt][1] * xv;
                float zg = acc[8 + cell * 2] + bi_r[ug][nt][2] + wi_r[ug][nt][2] * xv;
                float zo = acc[9 + cell * 2] + bi_r[ug][nt][3] + wi_r[ug][nt][3] * xv;
                float cp = cst[ug][cell];
                float cn = siga(zf) * cp + siga(zi) * tanha(zg);
                float hn = siga(zo) * tanha(cn);
                cst[ug][cell] = cn;
                int u = cg * 16 + ug * 8 + nt * 4 + (lane & 3);
                if (!last) {
                    uint32_t addr = wbuf + row * 256 + (((uint32_t)(2 * u)) ^ ((row & 7) << 4));
                    __half hh = __float2half(hn);
                    asm volatile("st.shared.b16 [%0], %1;"
                                 :: "r"(addr), "h"(*(unsigned short*)&hh));
                } else {
                    int ng = n0 + row;
                    if (hq < 8) g_q[((size_t)hq * NSEQ + ng) * HID + u] = hn;
                    else        g_kT[((size_t)(hq - 8) * HID + u) * NSEQ + ng] = hn;
                }
            }
        }
        // band-private barrier: h(t+1) stores visible to the band's 8 warps
        asm volatile("bar.sync %0, 256;" :: "r"(bar_id) : "memory");
    }
}

// ---------------- fused attention: scores + leaky + mask + softmax + attn@v + leaky ----------------
__global__ void k_attn(const float* __restrict__ graph, float* __restrict__ out) {
    int h = blockIdx.z, b = blockIdx.y, s0 = blockIdx.x * 16;
    int tid = threadIdx.x;
    __shared__ float qs[16][HID];
    __shared__ float sc[16][328];

    for (int i = tid; i < 16 * HID; i += 256) {
        int sq = i >> 7, d = i & 127;
        int s = s0 + sq;
        qs[sq][d] = (s < SLEN) ? g_q[((size_t)h * NSEQ + b * SLEN + s) * HID + d] : 0.f;
    }
    __syncthreads();

    for (int t = tid; t < SLEN; t += 256) {
        float acc[16];
#pragma unroll
        for (int i = 0; i < 16; i++) acc[i] = 0.f;
        const float* kp = g_kT + (size_t)h * HID * NSEQ + b * SLEN + t;
        for (int d = 0; d < HID; d += 4) {
            float k0 = kp[(size_t)d * NSEQ];
            float k1 = kp[(size_t)(d + 1) * NSEQ];
            float k2 = kp[(size_t)(d + 2) * NSEQ];
            float k3 = kp[(size_t)(d + 3) * NSEQ];
#pragma unroll
            for (int sq = 0; sq < 16; sq++) {
                float4 q4 = *reinterpret_cast<const float4*>(&qs[sq][d]);
                acc[sq] += k0 * q4.x + k1 * q4.y + k2 * q4.z + k3 * q4.w;
            }
        }
#pragma unroll
        for (int sq = 0; sq < 16; sq++) {
            int s = s0 + sq;
            float v = acc[sq] * SCALE;
            v = v >= 0.f ? v : 0.2f * v;
            bool keep = (s < SLEN) && ((s == t) || (graph[t * SLEN + s] != 0.f));
            sc[sq][t] = keep ? v : -1e9f;
        }
    }
    __syncthreads();

    {
        int r = tid >> 4, ln = tid & 15;
        float mx = -3.4e38f;
        for (int i = ln; i < SLEN; i += 16) mx = fmaxf(mx, sc[r][i]);
#pragma unroll
        for (int o = 1; o < 16; o <<= 1) mx = fmaxf(mx, __shfl_xor_sync(0xffffffffu, mx, o));
        float sum = 0.f;
        for (int i = ln; i < SLEN; i += 16) {
            float e = __expf(sc[r][i] - mx);
            sc[r][i] = e;
            sum += e;
        }
#pragma unroll
        for (int o = 1; o < 16; o <<= 1) sum += __shfl_xor_sync(0xffffffffu, sum, o);
        float inv = 1.f / sum;
        for (int i = ln; i < SLEN; i += 16) sc[r][i] *= inv;
    }
    __syncthreads();

    {
        int lg = tid & 63, sg = tid >> 6;
        float a2[4][3];
#pragma unroll
        for (int ss = 0; ss < 4; ss++) { a2[ss][0] = 0.f; a2[ss][1] = 0.f; a2[ss][2] = 0.f; }
        const float* vb = g_v + ((size_t)h * NSEQ + b * SLEN) * LSTEPS;
        for (int t = 0; t < SLEN; t++) {
            float a[4];
#pragma unroll
            for (int ss = 0; ss < 4; ss++) a[ss] = sc[sg * 4 + ss][t];
            const float* vr = vb + (size_t)t * LSTEPS + lg * 3;
            float v0 = vr[0], v1 = vr[1], v2 = vr[2];
#pragma unroll
            for (int ss = 0; ss < 4; ss++) {
                a2[ss][0] += a[ss] * v0;
                a2[ss][1] += a[ss] * v1;
                a2[ss][2] += a[ss] * v2;
            }
        }
#pragma unroll
        for (int ss = 0; ss < 4; ss++) {
            int s = s0 + sg * 4 + ss;
            if (s < SLEN) {
#pragma unroll
                for (int q = 0; q < 3; q++) {
                    float vv = a2[ss][q];
                    vv = vv >= 0.f ? vv : 0.2f * vv;
                    int l = lg * 3 + q;
                    out[(((size_t)(b * SLEN + s)) * LSTEPS + l) * NH + h] = vv;
                }
            }
        }
    }
}

// ---------------- launch ----------------
extern "C" void kernel_launch(void* const* d_in, const int* in_sizes, int n_in,
                              void* d_out, int out_size) {
    const float* x     = (const float*)d_in[0];
    const float* graph = (const float*)d_in[1];
    const float* qWih  = (const float*)d_in[2];
    const float* qWhh  = (const float*)d_in[3];
    const float* qbih  = (const float*)d_in[4];
    const float* qbhh  = (const float*)d_in[5];
    const float* kWih  = (const float*)d_in[6];
    const float* kWhh  = (const float*)d_in[7];
    const float* kbih  = (const float*)d_in[8];
    const float* kbhh  = (const float*)d_in[9];
    const float* vWih  = (const float*)d_in[10];
    const float* vWhh  = (const float*)d_in[11];
    const float* vbih  = (const float*)d_in[12];
    const float* vbhh  = (const float*)d_in[13];
    float* out = (float*)d_out;

    cudaFuncSetAttribute(k_qk_mma, cudaFuncAttributeMaxDynamicSharedMemorySize, SM_TOT);

    k_prep_x<<<(LSTEPS * NSEQ + 255) / 256, 256>>>(x);
    k_prep_w16<<<(16 * 512 * HID + 255) / 256, 256>>>(qWih, qWhh, qbih, qbhh,
                                                      kWih, kWhh, kbih, kbhh);
    k_v_lstm<<<(NH * NSEQ + 255) / 256, 256>>>(vWih, vWhh, vbih, vbhh);
    k_qk_mma<<<dim3(325, 16, 1), 512, SM_TOT>>>();
    k_attn<<<dim3(21, NB, NH), 256>>>(graph, out);
}